// round 1
// baseline (speedup 1.0000x reference)
#include <cuda_runtime.h>

// ---------------------------------------------------------------------------
// ChnAttn: tokens -> proj_in -> K,V -> 1-query masked attention -> proj_out
// B=4,H=16,W=16,T=8 -> BN=8192 ; N=5 tokens ; D=768 ; A=256 ; 8 heads x 32
// ---------------------------------------------------------------------------

#define BN_TOT 8192
#define NTOK   5
#define DDIM   768
#define ADIM   256
#define NROWS  (BN_TOT * NTOK)   // 40960

typedef unsigned long long ull;

// Scratch (device globals: allocation-free rule)
__device__ float g_X[(size_t)NROWS * ADIM];   // proj_in result (active rows only)
__device__ float g_Kd[(size_t)NROWS * ADIM];  // keys
__device__ float g_Vd[(size_t)NROWS * ADIM];  // values
__device__ float g_OA[(size_t)BN_TOT * ADIM]; // attention output
__device__ int   g_list[NROWS];               // compacted active row ids
__device__ int   g_flag[BN_TOT];              // has_encoder per bn
__device__ int   g_cnt;

// ---------------- f32x2 helpers (packed-pair FMA: 2x FFMA throughput) ------
__device__ __forceinline__ ull pack2(float lo, float hi) {
    ull r;
    asm("mov.b64 %0, {%1, %2};" : "=l"(r) : "f"(lo), "f"(hi));
    return r;
}
__device__ __forceinline__ void unpack2(ull v, float& lo, float& hi) {
    asm("mov.b64 {%0, %1}, %2;" : "=f"(lo), "=f"(hi) : "l"(v));
}
__device__ __forceinline__ void fma2(ull& d, ull a, ull b) {
    asm("fma.rn.f32x2 %0, %1, %2, %0;" : "+l"(d) : "l"(a), "l"(b));
}

// ---------------- setup kernels --------------------------------------------
__global__ void k_reset() { g_cnt = 0; }

__global__ void k_build(const int* __restrict__ s2m, const int* __restrict__ s1m,
                        float* __restrict__ maskout, int write_mask) {
    int bn = blockIdx.x * blockDim.x + threadIdx.x;
    if (bn >= BN_TOT) return;
    int has = 0;
#pragma unroll
    for (int n = 0; n < 5; n++) {
        int m = (n < 3) ? s2m[bn * 3 + n] : s1m[bn * 2 + (n - 3)];
        if (m == 1) {
            int p = atomicAdd(&g_cnt, 1);
            g_list[p] = bn * 5 + n;
            has = 1;
        }
    }
    g_flag[bn] = has;
    if (write_mask) maskout[bn] = has ? 1.0f : 0.0f;
}

// ---------------- GEMM core -------------------------------------------------
// 128x128 CTA tile, BK=16, 256 threads, each thread owns 8x8 outputs stored as
// 4x8 f32x2 accumulators (pairs along M). Smem tiles stored k-major-outer
// (As[k][m], Bs[k][n]) so M/N fragments are contiguous.
#define TBK 16

__device__ __forceinline__ void mma_chunk16(const float* __restrict__ As,
                                            const float* __restrict__ Bs,
                                            ull (&c)[4][8], int tm, int tn) {
#pragma unroll
    for (int kk = 0; kk < TBK; kk++) {
        const float* ap = As + kk * 128 + tm;
        ull aa[4];
        aa[0] = *(const ull*)(ap + 0);
        aa[1] = *(const ull*)(ap + 2);
        aa[2] = *(const ull*)(ap + 4);
        aa[3] = *(const ull*)(ap + 6);
        const float4 b0 = *(const float4*)(Bs + kk * 128 + tn);
        const float4 b1 = *(const float4*)(Bs + kk * 128 + tn + 4);
        ull bb[8];
        bb[0] = pack2(b0.x, b0.x); bb[1] = pack2(b0.y, b0.y);
        bb[2] = pack2(b0.z, b0.z); bb[3] = pack2(b0.w, b0.w);
        bb[4] = pack2(b1.x, b1.x); bb[5] = pack2(b1.y, b1.y);
        bb[6] = pack2(b1.z, b1.z); bb[7] = pack2(b1.w, b1.w);
#pragma unroll
        for (int i = 0; i < 4; i++)
#pragma unroll
            for (int j = 0; j < 8; j++)
                fma2(c[i][j], aa[i], bb[j]);
    }
}

// MODE 0: X = gather(tokens) @ W_in^T + b_in          (K=768, N=256)
// MODE 1: [K|V] = gather(X) @ [W_k|W_v]^T + b         (K=256, N=512)
// MODE 2: Out = OA @ W_out^T + b_out, zero if !flag   (K=256, N=768)
template <int MODE>
__global__ __launch_bounds__(256) void gemm_kernel(
    const float* __restrict__ s2, const float* __restrict__ s1,
    const float* __restrict__ W0, const float* __restrict__ bias0,
    const float* __restrict__ W1, const float* __restrict__ bias1,
    float* __restrict__ Out) {
    const int Kdim = (MODE == 0) ? DDIM : ADIM;
    const int mt = blockIdx.y;
    const int c0 = blockIdx.x * 128;
    const int cnt = (MODE == 2) ? BN_TOT : g_cnt;
    if (mt * 128 >= cnt) return;

    __shared__ __align__(16) float As[2][TBK * 128];
    __shared__ __align__(16) float Bs[2][TBK * 128];

    const int tid = threadIdx.x;
    const int tx = tid & 15, ty = tid >> 4;
    const int tm = ty * 8, tn = tx * 8;

    // Per-thread load assignment: quads q = 2*tid, 2*tid+1 (512 float4 per tile)
    const float* aptr[2];
    const float* bptr[2];
    int kq[2];
#pragma unroll
    for (int i = 0; i < 2; i++) {
        int q = 2 * tid + i;
        int lr = q >> 2;
        kq[i] = (q & 3) * 4;
        int p = mt * 128 + lr;
        if (MODE == 2) {
            aptr[i] = g_OA + (size_t)p * ADIM;
        } else if (p < cnt) {
            int r = g_list[p];
            if (MODE == 0) {
                int bn = r / 5, n = r - bn * 5;
                aptr[i] = (n < 3) ? s2 + (size_t)(bn * 3 + n) * DDIM
                                  : s1 + (size_t)(bn * 2 + (n - 3)) * DDIM;
            } else {
                aptr[i] = g_X + (size_t)r * ADIM;
            }
        } else {
            aptr[i] = nullptr;
        }
        int col = c0 + lr;
        if (MODE == 0)
            bptr[i] = W0 + (size_t)col * DDIM;
        else if (MODE == 1)
            bptr[i] = (col < ADIM) ? W0 + (size_t)col * ADIM
                                   : W1 + (size_t)(col - ADIM) * ADIM;
        else
            bptr[i] = W0 + (size_t)col * ADIM;
    }

    ull c[4][8];
#pragma unroll
    for (int i = 0; i < 4; i++)
#pragma unroll
        for (int j = 0; j < 8; j++) c[i][j] = 0ull;

    float4 ra[2], rb[2];
    const int nc = Kdim / TBK;

    // stage 0
#pragma unroll
    for (int i = 0; i < 2; i++) {
        ra[i] = aptr[i] ? *(const float4*)(aptr[i] + kq[i]) : make_float4(0, 0, 0, 0);
        rb[i] = *(const float4*)(bptr[i] + kq[i]);
    }
#pragma unroll
    for (int i = 0; i < 2; i++) {
        int q = 2 * tid + i;
        int lr = q >> 2, k0 = (q & 3) * 4;
        float* da = &As[0][k0 * 128 + lr];
        da[0] = ra[i].x; da[128] = ra[i].y; da[256] = ra[i].z; da[384] = ra[i].w;
        float* db = &Bs[0][k0 * 128 + lr];
        db[0] = rb[i].x; db[128] = rb[i].y; db[256] = rb[i].z; db[384] = rb[i].w;
    }
    __syncthreads();

    for (int ch = 0; ch < nc; ch++) {
        int cur = ch & 1;
        if (ch + 1 < nc) {
            int kt = (ch + 1) * TBK;
#pragma unroll
            for (int i = 0; i < 2; i++) {
                ra[i] = aptr[i] ? *(const float4*)(aptr[i] + kt + kq[i])
                                : make_float4(0, 0, 0, 0);
                rb[i] = *(const float4*)(bptr[i] + kt + kq[i]);
            }
        }
        mma_chunk16(As[cur], Bs[cur], c, tm, tn);
        if (ch + 1 < nc) {
            int nb = cur ^ 1;
#pragma unroll
            for (int i = 0; i < 2; i++) {
                int q = 2 * tid + i;
                int lr = q >> 2, k0 = (q & 3) * 4;
                float* da = &As[nb][k0 * 128 + lr];
                da[0] = ra[i].x; da[128] = ra[i].y; da[256] = ra[i].z; da[384] = ra[i].w;
                float* db = &Bs[nb][k0 * 128 + lr];
                db[0] = rb[i].x; db[128] = rb[i].y; db[256] = rb[i].z; db[384] = rb[i].w;
            }
        }
        __syncthreads();
    }

    // epilogue
    float bv[8];
#pragma unroll
    for (int j = 0; j < 8; j++) {
        int col = c0 + tn + j;
        if (MODE == 1)
            bv[j] = (col < ADIM) ? bias0[col] : bias1[col - ADIM];
        else
            bv[j] = bias0[col];
    }
#pragma unroll
    for (int i = 0; i < 8; i++) {
        int p = mt * 128 + tm + i;
        if (p >= cnt) break;
        float vals[8];
#pragma unroll
        for (int j = 0; j < 8; j++) {
            float lo, hi;
            unpack2(c[i >> 1][j], lo, hi);
            vals[j] = ((i & 1) ? hi : lo) + bv[j];
        }
        if (MODE == 0) {
            int r = g_list[p];
            float4* d = (float4*)(g_X + (size_t)r * ADIM + c0 + tn);
            d[0] = make_float4(vals[0], vals[1], vals[2], vals[3]);
            d[1] = make_float4(vals[4], vals[5], vals[6], vals[7]);
        } else if (MODE == 1) {
            int r = g_list[p];
            int col = c0 + tn;
            float* base = (col < ADIM) ? (g_Kd + (size_t)r * ADIM + col)
                                       : (g_Vd + (size_t)r * ADIM + (col - ADIM));
            ((float4*)base)[0] = make_float4(vals[0], vals[1], vals[2], vals[3]);
            ((float4*)base)[1] = make_float4(vals[4], vals[5], vals[6], vals[7]);
        } else {
            if (!g_flag[p]) {
#pragma unroll
                for (int j = 0; j < 8; j++) vals[j] = 0.0f;
            }
            float4* d = (float4*)(Out + (size_t)p * DDIM + c0 + tn);
            d[0] = make_float4(vals[0], vals[1], vals[2], vals[3]);
            d[1] = make_float4(vals[4], vals[5], vals[6], vals[7]);
        }
    }
}

// ---------------- attention (1 thread per (bn, head)) ----------------------
__global__ __launch_bounds__(256) void attn_kernel(const float* __restrict__ query,
                                                   const int* __restrict__ s2m,
                                                   const int* __restrict__ s1m) {
    int t = blockIdx.x * 256 + threadIdx.x;
    int bn = t >> 3, h = t & 7;
    bool act[5];
    bool has = false;
#pragma unroll
    for (int n = 0; n < 5; n++) {
        int m = (n < 3) ? s2m[bn * 3 + n] : s1m[bn * 2 + (n - 3)];
        act[n] = (m == 1);
        has |= act[n];
    }
    float* oa = g_OA + (size_t)bn * ADIM + h * 32;
    if (!has) {
#pragma unroll
        for (int d = 0; d < 32; d += 4) *(float4*)(oa + d) = make_float4(0, 0, 0, 0);
        return;
    }
    const float scale = 0.17677669529663687f;  // 32^{-1/2}
    float q[32];
#pragma unroll
    for (int d = 0; d < 32; d += 4) {
        float4 v = *(const float4*)(query + h * 32 + d);
        q[d] = v.x * scale; q[d + 1] = v.y * scale;
        q[d + 2] = v.z * scale; q[d + 3] = v.w * scale;
    }
    size_t r0 = (size_t)bn * 5;
    float l[5];
    float mx = -3.0e38f;
#pragma unroll
    for (int n = 0; n < 5; n++) {
        if (act[n]) {
            const float* kr = g_Kd + (r0 + n) * ADIM + h * 32;
            float s = 0.0f;
#pragma unroll
            for (int d = 0; d < 32; d += 4) {
                float4 kv = *(const float4*)(kr + d);
                s = fmaf(q[d], kv.x, s);
                s = fmaf(q[d + 1], kv.y, s);
                s = fmaf(q[d + 2], kv.z, s);
                s = fmaf(q[d + 3], kv.w, s);
            }
            l[n] = s;
            mx = fmaxf(mx, s);
        }
    }
    float w[5];
    float sum = 0.0f;
#pragma unroll
    for (int n = 0; n < 5; n++) {
        w[n] = act[n] ? __expf(l[n] - mx) : 0.0f;
        sum += w[n];
    }
    float inv = 1.0f / sum;
    float o[32];
#pragma unroll
    for (int d = 0; d < 32; d++) o[d] = 0.0f;
#pragma unroll
    for (int n = 0; n < 5; n++) {
        if (act[n]) {
            const float* vr = g_Vd + (r0 + n) * ADIM + h * 32;
#pragma unroll
            for (int d = 0; d < 32; d += 4) {
                float4 vv = *(const float4*)(vr + d);
                o[d] = fmaf(w[n], vv.x, o[d]);
                o[d + 1] = fmaf(w[n], vv.y, o[d + 1]);
                o[d + 2] = fmaf(w[n], vv.z, o[d + 2]);
                o[d + 3] = fmaf(w[n], vv.w, o[d + 3]);
            }
        }
    }
#pragma unroll
    for (int d = 0; d < 32; d += 4)
        *(float4*)(oa + d) = make_float4(o[d] * inv, o[d + 1] * inv,
                                         o[d + 2] * inv, o[d + 3] * inv);
}

// ---------------- launch ----------------------------------------------------
extern "C" void kernel_launch(void* const* d_in, const int* in_sizes, int n_in,
                              void* d_out, int out_size) {
    const float* s2    = (const float*)d_in[0];
    const float* s1    = (const float*)d_in[1];
    const float* W_in  = (const float*)d_in[2];
    const float* b_in  = (const float*)d_in[3];
    const float* W_k   = (const float*)d_in[4];
    const float* b_k   = (const float*)d_in[5];
    const float* W_v   = (const float*)d_in[6];
    const float* b_v   = (const float*)d_in[7];
    const float* W_out = (const float*)d_in[8];
    const float* b_out = (const float*)d_in[9];
    const float* query = (const float*)d_in[10];
    const int* s2m     = (const int*)d_in[11];
    const int* s1m     = (const int*)d_in[12];
    float* out = (float*)d_out;

    const int OUT_MAIN = BN_TOT * DDIM;  // 6291456
    int write_mask = (out_size > OUT_MAIN) ? 1 : 0;

    k_reset<<<1, 1>>>();
    k_build<<<BN_TOT / 256, 256>>>(s2m, s1m, out + (size_t)OUT_MAIN, write_mask);
    gemm_kernel<0><<<dim3(ADIM / 128, NROWS / 128), 256>>>(s2, s1, W_in, b_in,
                                                           nullptr, nullptr, nullptr);
    gemm_kernel<1><<<dim3(2 * ADIM / 128, NROWS / 128), 256>>>(nullptr, nullptr, W_k,
                                                               b_k, W_v, b_v, nullptr);
    attn_kernel<<<BN_TOT * 8 / 256, 256>>>(query, s2m, s1m);
    gemm_kernel<2><<<dim3(DDIM / 128, BN_TOT / 128), 256>>>(nullptr, nullptr, W_out,
                                                            b_out, nullptr, nullptr, out);
}

// round 16
// speedup vs baseline: 1.0107x; 1.0107x over previous
#include <cuda_runtime.h>
#include <cuda_bf16.h>
#include <cstdint>

// ---------------------------------------------------------------------------
// ChnAttn via mma.sync (baseline PTX, HMMA): tokens -> proj_in -> K,V ->
// masked 1-query attention -> proj_out.
// All GEMMs: bf16 3-term split (AhiBhi + AhiBlo + AloBhi), fp32 reg accum.
// tcgen05 is rejected by the harness's compute_103 (no 'a') ptxas target;
// mma.sync/ldmatrix are sm_80+ baseline and safe.
// ---------------------------------------------------------------------------

typedef unsigned long long ull;
typedef unsigned int u32;

#define BN_TOT 8192
#define DDIM   768
#define ADIM   256
#define NROWS  40960

#define WOFF_IN  0
#define WOFF_K   196608
#define WOFF_V   262144
#define WOFF_OUT 327680

// ---------------- scratch (device globals: allocation-free rule) -----------
__device__ __nv_bfloat16 g_Xhi[(size_t)NROWS * ADIM];
__device__ __nv_bfloat16 g_Xlo[(size_t)NROWS * ADIM];
__device__ __nv_bfloat16 g_Whi[524288];
__device__ __nv_bfloat16 g_Wlo[524288];
__device__ float g_Kc[(size_t)NROWS * ADIM];
__device__ float g_Vc[(size_t)NROWS * ADIM];
__device__ float g_OA[(size_t)BN_TOT * ADIM];
__device__ int   g_list[NROWS];
__device__ int   g_pos[NROWS];
__device__ int   g_flag[BN_TOT];
__device__ int   g_cnt;

// ---------------- PTX helpers (baseline ISA only) ---------------------------
__device__ __forceinline__ u32 smem_u32(const void* p) {
    u32 a;
    asm("{ .reg .u64 t; cvta.to.shared.u64 t, %1; cvt.u32.u64 %0, t; }" : "=r"(a) : "l"(p));
    return a;
}
__device__ __forceinline__ void ldsm4(u32* r, u32 a) {
    asm volatile("ldmatrix.sync.aligned.m8n8.x4.shared.b16 {%0,%1,%2,%3}, [%4];"
                 : "=r"(r[0]), "=r"(r[1]), "=r"(r[2]), "=r"(r[3]) : "r"(a));
}
__device__ __forceinline__ void mma16816(float* d, const u32* a, const u32* b) {
    asm volatile("mma.sync.aligned.m16n8k16.row.col.f32.bf16.bf16.f32 "
                 "{%0,%1,%2,%3},{%4,%5,%6,%7},{%8,%9},{%0,%1,%2,%3};"
                 : "+f"(d[0]), "+f"(d[1]), "+f"(d[2]), "+f"(d[3])
                 : "r"(a[0]), "r"(a[1]), "r"(a[2]), "r"(a[3]), "r"(b[0]), "r"(b[1]));
}

// ---------------- setup kernels --------------------------------------------
__global__ void k_reset() { g_cnt = 0; }

__global__ void k_build(const int* __restrict__ s2m, const int* __restrict__ s1m,
                        float* __restrict__ maskout, int write_mask) {
    int bn = blockIdx.x * blockDim.x + threadIdx.x;
    if (bn >= BN_TOT) return;
    int has = 0;
#pragma unroll
    for (int n = 0; n < 5; n++) {
        int m = (n < 3) ? s2m[bn * 3 + n] : s1m[bn * 2 + (n - 3)];
        if (m == 1) {
            int p = atomicAdd(&g_cnt, 1);
            g_list[p] = bn * 5 + n;
            g_pos[bn * 5 + n] = p;
            has = 1;
        }
    }
    g_flag[bn] = has;
    if (write_mask) maskout[bn] = has ? 1.0f : 0.0f;
}

__global__ void k_cvtw(const float* __restrict__ src, int off, int n) {
    int i = blockIdx.x * 256 + threadIdx.x;
    if (i >= n) return;
    float x = src[i];
    __nv_bfloat16 h = __float2bfloat16(x);
    g_Whi[off + i] = h;
    g_Wlo[off + i] = __float2bfloat16(x - __bfloat162float(h));
}

// ---------------- conversion helpers ---------------------------------------
__device__ __forceinline__ ull pack4(__nv_bfloat16 a, __nv_bfloat16 b,
                                     __nv_bfloat16 c, __nv_bfloat16 d) {
    union { ull u; __nv_bfloat16 h[4]; } p;
    p.h[0] = a; p.h[1] = b; p.h[2] = c; p.h[3] = d;
    return p.u;
}
__device__ __forceinline__ void cvt4(float4 v, ull& hi, ull& lo) {
    __nv_bfloat16 h0 = __float2bfloat16(v.x);
    __nv_bfloat16 h1 = __float2bfloat16(v.y);
    __nv_bfloat16 h2 = __float2bfloat16(v.z);
    __nv_bfloat16 h3 = __float2bfloat16(v.w);
    hi = pack4(h0, h1, h2, h3);
    lo = pack4(__float2bfloat16(v.x - __bfloat162float(h0)),
               __float2bfloat16(v.y - __bfloat162float(h1)),
               __float2bfloat16(v.z - __bfloat162float(h2)),
               __float2bfloat16(v.w - __bfloat162float(h3)));
}

// ---------------- mma.sync GEMM --------------------------------------------
// CTA 128x128, BK=64, 256 thr = 8 warps (2 M x 4 N), warp tile 64x32.
// Smem rows padded to 72 bf16 (144B) -> conflict-free ldmatrix.
// A smem: [m-row][k];  B smem: [n-col][k] (= col-major kxN -> NON-trans ldmatrix).
// MODE 0: A = gather(tokens) fp32->cvt     K=768   out: X hi/lo (compact p)
// MODE 1: A = X (bf16 hi/lo, compact p)    K=256   out: K|V fp32 (compact p)
// MODE 2: A = OA fp32->cvt                 K=256   out: final (+bias, flag-zero)
#define BK 64
#define RSTRIDE 144
#define SOFF_AHI 0
#define SOFF_ALO 18432
#define SOFF_BHI 36864
#define SOFF_BLO 55296
#define SMEM_TOTAL 73728

template <int MODE>
__global__ __launch_bounds__(256) void gemm_mma(
    const float* __restrict__ s2, const float* __restrict__ s1,
    const float* __restrict__ bias_a, const float* __restrict__ bias_b,
    float* __restrict__ Out) {
    const int Kdim = (MODE == 0) ? DDIM : ADIM;
    const int NCH = Kdim / BK;
    const int mtile = blockIdx.y;
    const int c0 = blockIdx.x * 128;
    const int cnt = (MODE == 2) ? BN_TOT : g_cnt;
    if (mtile * 128 >= cnt) return;

    extern __shared__ char smem[];
    const u32 sb = smem_u32(smem);
    const int tid = threadIdx.x;
    const int lid = tid & 31, wid = tid >> 5;
    const int wm = wid >> 2, wn = wid & 3;

    // ---- gmem load assignment: thread -> (row, half of 64-k chunk) --------
    const int lrow = tid >> 1, lhalf = tid & 1;
    const int p_l = mtile * 128 + lrow;
    const ptrdiff_t dXlo = (const char*)g_Xlo - (const char*)g_Xhi;
    const ptrdiff_t dWlo = (const char*)g_Wlo - (const char*)g_Whi;

    const float* afp = nullptr;
    const ull* axh = nullptr;
    if (MODE == 0) {
        if (p_l < cnt) {
            int r = g_list[p_l];
            int bn = r / 5, n = r - bn * 5;
            afp = (n < 3) ? s2 + (size_t)(bn * 3 + n) * DDIM
                          : s1 + (size_t)(bn * 2 + (n - 3)) * DDIM;
        }
    } else if (MODE == 2) {
        afp = g_OA + (size_t)p_l * ADIM;
    } else {
        if (p_l < cnt) axh = (const ull*)(g_Xhi + (size_t)p_l * ADIM);
    }
    const int colB = c0 + lrow;
    size_t woff;
    if (MODE == 0) woff = WOFF_IN + (size_t)colB * DDIM;
    else if (MODE == 1) woff = (colB < ADIM) ? WOFF_K + (size_t)colB * ADIM
                                             : WOFF_V + (size_t)(colB - ADIM) * ADIM;
    else woff = WOFF_OUT + (size_t)colB * ADIM;
    const ull* bwh = (const ull*)(g_Whi + woff);

    const u32 lrow_off = (u32)lrow * RSTRIDE;

    // ---- fragment lane base addresses -------------------------------------
    // A (x4): lanes 0-7 rows 0-7 k0-7 | 8-15 rows 8-15 k0-7 | 16-23 rows 0-7 k8-15 | 24-31 rows 8-15 k8-15
    const u32 aBase = sb + SOFF_AHI + (u32)(wm * 64 + (lid & 15)) * RSTRIDE + (u32)(lid >> 4) * 16;
    // B (x4, NON-trans over [n][k] rows): lanes 0-7 n0-7 k0-7 | 8-15 n0-7 k8-15 | 16-23 n8-15 k0-7 | 24-31 n8-15 k8-15
    const u32 bBase = sb + SOFF_BHI + (u32)(wn * 32 + ((lid >> 4) << 3) + (lid & 7)) * RSTRIDE
                      + (u32)((lid >> 3) & 1) * 16;

    float acc[4][4][4];
#pragma unroll
    for (int i = 0; i < 4; i++)
#pragma unroll
        for (int j = 0; j < 4; j++)
#pragma unroll
            for (int k = 0; k < 4; k++) acc[i][j][k] = 0.0f;

    for (int ch = 0; ch < NCH; ch++) {
        // ---- A tile -> smem (hi/lo): 64 k-elems = 128B per row ------------
        if (MODE == 0 || MODE == 2) {
            const int kg = ch * BK + lhalf * 32;
#pragma unroll
            for (int j = 0; j < 8; j++) {
                float4 v = afp ? *(const float4*)(afp + kg + 4 * j)
                               : make_float4(0.f, 0.f, 0.f, 0.f);
                ull hi, lo;
                cvt4(v, hi, lo);
                u32 off = lrow_off + (u32)(lhalf * 64 + 8 * j);
                *(ull*)(smem + SOFF_AHI + off) = hi;
                *(ull*)(smem + SOFF_ALO + off) = lo;
            }
        } else {
            const int kq = ch * 16 + lhalf * 8;
#pragma unroll
            for (int j = 0; j < 8; j++) {
                ull hi = 0, lo = 0;
                if (axh) {
                    const ull* hp = axh + kq + j;
                    hi = *hp;
                    lo = *(const ull*)((const char*)hp + dXlo);
                }
                u32 off = lrow_off + (u32)(lhalf * 64 + 8 * j);
                *(ull*)(smem + SOFF_AHI + off) = hi;
                *(ull*)(smem + SOFF_ALO + off) = lo;
            }
        }
        // ---- B tile -> smem (hi/lo): 16 ulls per row-chunk ----------------
        {
            const int kq = ch * 16 + lhalf * 8;
#pragma unroll
            for (int j = 0; j < 8; j++) {
                const ull* hp = bwh + kq + j;
                u32 off = lrow_off + (u32)(lhalf * 64 + 8 * j);
                *(ull*)(smem + SOFF_BHI + off) = *hp;
                *(ull*)(smem + SOFF_BLO + off) = *(const ull*)((const char*)hp + dWlo);
            }
        }
        __syncthreads();

        // ---- compute: 4 k16 steps, 3 split terms --------------------------
#pragma unroll
        for (int ks = 0; ks < 4; ks++) {
            u32 ahi[4][4], alo[4][4];
#pragma unroll
            for (int mt = 0; mt < 4; mt++) {
                u32 aa = aBase + (u32)(mt * 16 * RSTRIDE) + (u32)(ks * 32);
                ldsm4(ahi[mt], aa);
                ldsm4(alo[mt], aa + (SOFF_ALO - SOFF_AHI));
            }
#pragma unroll
            for (int np = 0; np < 2; np++) {
                u32 ba = bBase + (u32)(np * 16 * RSTRIDE) + (u32)(ks * 32);
                u32 bhi[4], blo[4];
                ldsm4(bhi, ba);                             // non-trans: [n][k] IS col-major k x n
                ldsm4(blo, ba + (SOFF_BLO - SOFF_BHI));
#pragma unroll
                for (int mt = 0; mt < 4; mt++) {
                    mma16816(acc[mt][np * 2], ahi[mt], bhi);
                    mma16816(acc[mt][np * 2], ahi[mt], blo);
                    mma16816(acc[mt][np * 2], alo[mt], bhi);
                    mma16816(acc[mt][np * 2 + 1], ahi[mt], bhi + 2);
                    mma16816(acc[mt][np * 2 + 1], ahi[mt], blo + 2);
                    mma16816(acc[mt][np * 2 + 1], alo[mt], bhi + 2);
                }
            }
        }
        __syncthreads();
    }

    // ---- epilogue: d-frag lane mapping (row g / g+8, cols 2c,2c+1) --------
    const int g = lid >> 2, c2 = (lid & 3) * 2;
#pragma unroll
    for (int mt = 0; mt < 4; mt++) {
#pragma unroll
        for (int half = 0; half < 2; half++) {
            const int r = wm * 64 + mt * 16 + g + half * 8;
            const int p = mtile * 128 + r;
            if (p >= cnt) continue;
            const int fl = (MODE == 2) ? g_flag[p] : 1;
#pragma unroll
            for (int nt = 0; nt < 4; nt++) {
                const int col = c0 + wn * 32 + nt * 8 + c2;
                float v0 = acc[mt][nt][half * 2 + 0];
                float v1 = acc[mt][nt][half * 2 + 1];
                if (MODE == 0) {
                    v0 += bias_a[col];
                    v1 += bias_a[col + 1];
                    __nv_bfloat16 h0 = __float2bfloat16(v0);
                    __nv_bfloat16 h1 = __float2bfloat16(v1);
                    __nv_bfloat162 hh; hh.x = h0; hh.y = h1;
                    *(__nv_bfloat162*)(g_Xhi + (size_t)p * ADIM + col) = hh;
                    __nv_bfloat162 ll;
                    ll.x = __float2bfloat16(v0 - __bfloat162float(h0));
                    ll.y = __float2bfloat16(v1 - __bfloat162float(h1));
                    *(__nv_bfloat162*)(g_Xlo + (size_t)p * ADIM + col) = ll;
                } else if (MODE == 1) {
                    const bool isK = (c0 < ADIM);
                    const int bc = isK ? col : col - ADIM;
                    const float* bias = isK ? bias_a : bias_b;
                    float* dst = isK ? (g_Kc + (size_t)p * ADIM + bc)
                                     : (g_Vc + (size_t)p * ADIM + bc);
                    float2 o; o.x = v0 + bias[bc]; o.y = v1 + bias[bc + 1];
                    *(float2*)dst = o;
                } else {
                    float2 o;
                    o.x = fl ? (v0 + bias_a[col]) : 0.0f;
                    o.y = fl ? (v1 + bias_a[col + 1]) : 0.0f;
                    *(float2*)(Out + (size_t)p * DDIM + col) = o;
                }
            }
        }
    }
}

// ---------------- attention (1 thread per (bn, head)) ----------------------
__global__ __launch_bounds__(256) void attn_kernel(const float* __restrict__ query,
                                                   const int* __restrict__ s2m,
                                                   const int* __restrict__ s1m) {
    int t = blockIdx.x * 256 + threadIdx.x;
    int bn = t >> 3, h = t & 7;
    bool act[5];
    bool has = false;
#pragma unroll
    for (int n = 0; n < 5; n++) {
        int m = (n < 3) ? s2m[bn * 3 + n] : s1m[bn * 2 + (n - 3)];
        act[n] = (m == 1);
        has |= act[n];
    }
    float* oa = g_OA + (size_t)bn * ADIM + h * 32;
    if (!has) {
#pragma unroll
        for (int d = 0; d < 32; d += 4) *(float4*)(oa + d) = make_float4(0, 0, 0, 0);
        return;
    }
    const float scale = 0.17677669529663687f;  // 32^{-1/2}
    float q[32];
#pragma unroll
    for (int d = 0; d < 32; d += 4) {
        float4 v = *(const float4*)(query + h * 32 + d);
        q[d] = v.x * scale; q[d + 1] = v.y * scale;
        q[d + 2] = v.z * scale; q[d + 3] = v.w * scale;
    }
    int pp[5];
#pragma unroll
    for (int n = 0; n < 5; n++) pp[n] = act[n] ? g_pos[bn * 5 + n] : 0;

    float l[5];
    float mx = -3.0e38f;
#pragma unroll
    for (int n = 0; n < 5; n++) {
        if (act[n]) {
            const float* kr = g_Kc + (size_t)pp[n] * ADIM + h * 32;
            float s = 0.0f;
#pragma unroll
            for (int d = 0; d < 32; d += 4) {
                float4 kv = *(const float4*)(kr + d);
                s = fmaf(q[d], kv.x, s);
                s = fmaf(q[d + 1], kv.y, s);
                s = fmaf(q[d + 2], kv.z, s);
                s = fmaf(q[d + 3], kv.w, s);
            }
            l[n] = s;
            mx = fmaxf(mx, s);
        }
    }
    float w[5];
    float sum = 0.0f;
#pragma unroll
    for (int n = 0; n < 5; n++) {
        w[n] = act[n] ? __expf(l[n] - mx) : 0.0f;
        sum += w[n];
    }
    float inv = 1.0f / sum;
    float o[32];
#pragma unroll
    for (int d = 0; d < 32; d++) o[d] = 0.0f;
#pragma unroll
    for (int n = 0; n < 5; n++) {
        if (act[n]) {
            const float* vr = g_Vc + (size_t)pp[n] * ADIM + h * 32;
#pragma unroll
            for (int d = 0; d < 32; d += 4) {
                float4 vv = *(const float4*)(vr + d);
                o[d] = fmaf(w[n], vv.x, o[d]);
                o[d + 1] = fmaf(w[n], vv.y, o[d + 1]);
                o[d + 2] = fmaf(w[n], vv.z, o[d + 2]);
                o[d + 3] = fmaf(w[n], vv.w, o[d + 3]);
            }
        }
    }
#pragma unroll
    for (int d = 0; d < 32; d += 4)
        *(float4*)(oa + d) = make_float4(o[d] * inv, o[d + 1] * inv,
                                         o[d + 2] * inv, o[d + 3] * inv);
}

// ---------------- launch ----------------------------------------------------
extern "C" void kernel_launch(void* const* d_in, const int* in_sizes, int n_in,
                              void* d_out, int out_size) {
    const float* s2    = (const float*)d_in[0];
    const float* s1    = (const float*)d_in[1];
    const float* W_in  = (const float*)d_in[2];
    const float* b_in  = (const float*)d_in[3];
    const float* W_k   = (const float*)d_in[4];
    const float* b_k   = (const float*)d_in[5];
    const float* W_v   = (const float*)d_in[6];
    const float* b_v   = (const float*)d_in[7];
    const float* W_out = (const float*)d_in[8];
    const float* b_out = (const float*)d_in[9];
    const float* query = (const float*)d_in[10];
    const int* s2m     = (const int*)d_in[11];
    const int* s1m     = (const int*)d_in[12];
    float* out = (float*)d_out;

    cudaFuncSetAttribute(gemm_mma<0>, cudaFuncAttributeMaxDynamicSharedMemorySize, SMEM_TOTAL);
    cudaFuncSetAttribute(gemm_mma<1>, cudaFuncAttributeMaxDynamicSharedMemorySize, SMEM_TOTAL);
    cudaFuncSetAttribute(gemm_mma<2>, cudaFuncAttributeMaxDynamicSharedMemorySize, SMEM_TOTAL);

    const int OUT_MAIN = BN_TOT * DDIM;
    int write_mask = (out_size > OUT_MAIN) ? 1 : 0;

    k_reset<<<1, 1>>>();
    k_build<<<BN_TOT / 256, 256>>>(s2m, s1m, out + (size_t)OUT_MAIN, write_mask);
    k_cvtw<<<(196608 + 255) / 256, 256>>>(W_in, WOFF_IN, 196608);
    k_cvtw<<<(65536 + 255) / 256, 256>>>(W_k, WOFF_K, 65536);
    k_cvtw<<<(65536 + 255) / 256, 256>>>(W_v, WOFF_V, 65536);
    k_cvtw<<<(196608 + 255) / 256, 256>>>(W_out, WOFF_OUT, 196608);

    gemm_mma<0><<<dim3(2, NROWS / 128), 256, SMEM_TOTAL>>>(s2, s1, b_in, nullptr, nullptr);
    gemm_mma<1><<<dim3(4, NROWS / 128), 256, SMEM_TOTAL>>>(nullptr, nullptr, b_k, b_v, nullptr);
    attn_kernel<<<BN_TOT * 8 / 256, 256>>>(query, s2m, s1m);
    gemm_mma<2><<<dim3(6, BN_TOT / 128), 256, SMEM_TOTAL>>>(nullptr, nullptr, b_out, nullptr, out);
}